// round 3
// baseline (speedup 1.0000x reference)
#include <cuda_runtime.h>
#include <cuda_fp16.h>

// SAG: CSR SpMM neighbor aggregation, deg=16, D=48, fp32 in/out.
//
// R3: kernel is LTS(L2)-byte bound (R1 moved ~333MB in 25.8us = ~12.9TB/s,
// at the measured ~6300 B/cyc chip cap). Reduce bytes:
//   1. Pre-pass converts X to fp16 rows padded to 128B (one aligned line/row)
//      in a __device__ scratch array. Halves gather traffic (192B -> 96B/edge).
//   2. Warp-per-node gather: 24 lanes, one LDG.32(half2) per edge = 1 L1tex
//      wavefront, 3 L2 sectors, zero within-LDG replays, zero per-lane IMAD.
// Accumulation stays fp32 (error ~3e-4 norm-relative, under the 1e-3 bound).

#define N_CAP      100000
#define D_FEAT     48
#define ROW_H2     32        // padded row: 64 halves = 32 half2 = 128 bytes
#define USED_H2    24        // 48 halves = 24 half2 = 96 bytes used

__device__ __align__(128) __half2 g_Xh[(size_t)N_CAP * ROW_H2];

// ---- pre-pass: fp32 [n,48] -> fp16 [n,64(pad)] ------------------------------
__global__ void convert_kernel(const float* __restrict__ X, int n_nodes)
{
    int t = blockIdx.x * blockDim.x + threadIdx.x;       // one half2 slot
    int total = n_nodes * ROW_H2;
    if (t >= total) return;
    int row = t >> 5;            // /32
    int c   = t & 31;
    __half2 v;
    if (c < USED_H2) {
        const float2 f = reinterpret_cast<const float2*>(X + (size_t)row * D_FEAT)[c];
        v = __floats2half2_rn(f.x, f.y);
    } else {
        v = __floats2half2_rn(0.f, 0.f);
    }
    g_Xh[t] = v;
}

// ---- main: warp per destination node ---------------------------------------
__global__ __launch_bounds__(256, 8)
void sag_fp16_kernel(const int* __restrict__ row_pointers,
                     const int* __restrict__ column_index,
                     float* __restrict__ out,
                     int n_nodes)
{
    const int warp = (blockIdx.x * blockDim.x + threadIdx.x) >> 5;
    const int lane = threadIdx.x & 31;
    if (warp >= n_nodes) return;

    const int base = row_pointers[warp];
    const int deg  = row_pointers[warp + 1] - base;

    // lanes 0..15 fetch the 16 edge indices (coalesced), broadcast via shfl
    int my_idx = 0;
    if (lane < 16 && lane < deg) my_idx = column_index[base + lane];

    const bool active = (lane < USED_H2);
    float ax = 0.f, ay = 0.f;

    if (deg == 16) {
        #pragma unroll
        for (int e = 0; e < 16; ++e) {
            const int idx = __shfl_sync(0xffffffffu, my_idx, e);
            if (active) {
                const __half2 h = __ldg(g_Xh + ((size_t)idx << 5) + lane);
                const float2 f = __half22float2(h);
                ax += f.x; ay += f.y;
            }
        }
    } else {
        for (int e = 0; e < deg; ++e) {
            int idx;
            if (e < 16) idx = __shfl_sync(0xffffffffu, my_idx, e);
            else        idx = column_index[base + e];
            if (active) {
                const __half2 h = __ldg(g_Xh + ((size_t)idx << 5) + lane);
                const float2 f = __half22float2(h);
                ax += f.x; ay += f.y;
            }
        }
    }

    if (active) {
        reinterpret_cast<float2*>(out + (size_t)warp * D_FEAT)[lane] =
            make_float2(ax, ay);
    }
}

// ---- fp32 fallback (only if n_nodes exceeds the scratch capacity) ----------
__global__ __launch_bounds__(256, 8)
void sag_fp32_kernel(const float* __restrict__ X,
                     const int* __restrict__ row_pointers,
                     const int* __restrict__ column_index,
                     float* __restrict__ out,
                     int n_nodes)
{
    const int tid  = blockIdx.x * blockDim.x + threadIdx.x;
    const int node = tid >> 4;
    const int lane = tid & 15;
    if (node >= n_nodes) return;

    const int base = row_pointers[node];
    const int deg  = row_pointers[node + 1] - base;
    int my_idx = 0;
    if (lane < deg) my_idx = column_index[base + lane];

    float a0 = 0.f, a1 = 0.f, a2 = 0.f;
    for (int e = 0; e < deg; ++e) {
        int idx = (e < 16) ? __shfl_sync(0xffffffffu, my_idx, e, 16)
                           : column_index[base + e];
        const float* row = X + (size_t)idx * D_FEAT;
        a0 += __ldg(row + lane);
        a1 += __ldg(row + lane + 16);
        a2 += __ldg(row + lane + 32);
    }
    float* orow = out + (size_t)node * D_FEAT;
    orow[lane] = a0; orow[lane + 16] = a1; orow[lane + 32] = a2;
}

extern "C" void kernel_launch(void* const* d_in, const int* in_sizes, int n_in,
                              void* d_out, int out_size)
{
    const float* X   = (const float*)d_in[0];
    const int*   rp  = (const int*)d_in[1];
    const int*   col = (const int*)d_in[2];
    float*       out = (float*)d_out;

    const int n_nodes = in_sizes[1] - 1;

    if (n_nodes <= N_CAP) {
        // 1) convert X -> padded fp16 scratch
        {
            const int total = n_nodes * ROW_H2;
            const int threads = 256;
            convert_kernel<<<(total + threads - 1) / threads, threads>>>(X, n_nodes);
        }
        // 2) gather-sum in fp16, accumulate fp32
        {
            const int threads = 256;                 // 8 warps = 8 nodes/block
            const int blocks = (n_nodes + 7) / 8;
            sag_fp16_kernel<<<blocks, threads>>>(rp, col, out, n_nodes);
        }
    } else {
        const int threads = 256;
        const int blocks = (n_nodes * 16 + threads - 1) / threads;
        sag_fp32_kernel<<<blocks, threads>>>(X, rp, col, out, n_nodes);
    }
}

// round 4
// speedup vs baseline: 1.2443x; 1.2443x over previous
#include <cuda_runtime.h>
#include <cuda_fp16.h>

// SAG: CSR SpMM neighbor aggregation, deg=16, D=48, fp32 in/out.
//
// R4: chip is LTS-byte bound at ~12.6 TB/s (R1/R2 both plateaued there).
// Keep R3's fp16 byte reduction (96B/row vs 192B) but restore R1's
// instruction economy: 2 nodes per warp, 16 lanes per node, one LDG.64
// (4 halves) per lane per edge, pure 32-bit addressing (1 IMAD), fp32
// accumulators. ~11 warp-instructions per 192B gathered vs R3's ~13 per 96B.
// Unpadded 96B rows are 32B-aligned -> always exactly 3 L2 sectors/edge.

#define N_CAP   100000
#define D_FEAT  48
#define ROW_I2  12            // 96 B row = 12 int2 (4 halves each)

__device__ __align__(16) __half2 g_Xh[(size_t)N_CAP * 24];   // 9.6 MB scratch

// ---- pre-pass: fp32 [n,48] -> fp16 [n,48] (contiguous, vectorized) ---------
__global__ void convert_kernel(const float4* __restrict__ X4, int total4)
{
    int t = blockIdx.x * blockDim.x + threadIdx.x;   // one float4 -> one uint2
    if (t >= total4) return;
    const float4 f = __ldg(X4 + t);
    const __half2 a = __floats2half2_rn(f.x, f.y);
    const __half2 b = __floats2half2_rn(f.z, f.w);
    uint2 v;
    v.x = *reinterpret_cast<const unsigned int*>(&a);
    v.y = *reinterpret_cast<const unsigned int*>(&b);
    reinterpret_cast<uint2*>(g_Xh)[t] = v;
}

// ---- main: 2 nodes per warp, 16 lanes per node -----------------------------
__global__ __launch_bounds__(256, 8)
void sag_fp16_kernel(const int* __restrict__ row_pointers,
                     const int* __restrict__ column_index,
                     float* __restrict__ out,
                     int n_nodes)
{
    const int lane = threadIdx.x & 31;
    const int sub  = lane & 15;                         // lane within node group
    const int node = ((blockIdx.x * blockDim.x + threadIdx.x) >> 4);
    if (node >= n_nodes) return;

    const int base = row_pointers[node];
    const int deg  = row_pointers[node + 1] - base;

    // sub-lane e holds edge e's neighbor index (coalesced 64B per node)
    int my_idx = 0;
    if (sub < deg) my_idx = column_index[base + sub];

    const int2* __restrict__ Xi2 = reinterpret_cast<const int2*>(g_Xh);
    const bool active = (sub < ROW_I2);

    float a0 = 0.f, a1 = 0.f, a2 = 0.f, a3 = 0.f;

    if (deg == 16) {
        #pragma unroll
        for (int e = 0; e < 16; ++e) {
            // broadcast within each 16-lane segment
            const int idx = __shfl_sync(0xffffffffu, my_idx, e, 16);
            if (active) {
                const int2 v = __ldg(Xi2 + (idx * ROW_I2 + sub));  // 1 IMAD
                const float2 f0 = __half22float2(*reinterpret_cast<const __half2*>(&v.x));
                const float2 f1 = __half22float2(*reinterpret_cast<const __half2*>(&v.y));
                a0 += f0.x; a1 += f0.y; a2 += f1.x; a3 += f1.y;
            }
        }
    } else {
        for (int e = 0; e < deg; ++e) {
            int idx = (e < 16) ? __shfl_sync(0xffffffffu, my_idx, e, 16)
                               : column_index[base + e];
            if (active) {
                const int2 v = __ldg(Xi2 + (idx * ROW_I2 + sub));
                const float2 f0 = __half22float2(*reinterpret_cast<const __half2*>(&v.x));
                const float2 f1 = __half22float2(*reinterpret_cast<const __half2*>(&v.y));
                a0 += f0.x; a1 += f0.y; a2 += f1.x; a3 += f1.y;
            }
        }
    }

    if (active) {
        // lane sub holds feature dims [4*sub .. 4*sub+3]; out row = 12 float4
        reinterpret_cast<float4*>(out)[node * ROW_I2 + sub] =
            make_float4(a0, a1, a2, a3);
    }
}

// ---- fp32 fallback (only if n exceeds scratch capacity) --------------------
__global__ __launch_bounds__(256, 8)
void sag_fp32_kernel(const float* __restrict__ X,
                     const int* __restrict__ row_pointers,
                     const int* __restrict__ column_index,
                     float* __restrict__ out,
                     int n_nodes)
{
    const int tid  = blockIdx.x * blockDim.x + threadIdx.x;
    const int node = tid >> 4;
    const int lane = tid & 15;
    if (node >= n_nodes) return;

    const int base = row_pointers[node];
    const int deg  = row_pointers[node + 1] - base;
    int my_idx = 0;
    if (lane < deg) my_idx = column_index[base + lane];

    float a0 = 0.f, a1 = 0.f, a2 = 0.f;
    for (int e = 0; e < deg; ++e) {
        int idx = (e < 16) ? __shfl_sync(0xffffffffu, my_idx, e, 16)
                           : column_index[base + e];
        const float* row = X + (size_t)idx * D_FEAT;
        a0 += __ldg(row + lane);
        a1 += __ldg(row + lane + 16);
        a2 += __ldg(row + lane + 32);
    }
    float* orow = out + (size_t)node * D_FEAT;
    orow[lane] = a0; orow[lane + 16] = a1; orow[lane + 32] = a2;
}

extern "C" void kernel_launch(void* const* d_in, const int* in_sizes, int n_in,
                              void* d_out, int out_size)
{
    const float* X   = (const float*)d_in[0];
    const int*   rp  = (const int*)d_in[1];
    const int*   col = (const int*)d_in[2];
    float*       out = (float*)d_out;

    const int n_nodes = in_sizes[1] - 1;

    if (n_nodes <= N_CAP) {
        {
            const int total4 = n_nodes * (D_FEAT / 4);      // 1.2M float4
            const int threads = 256;
            convert_kernel<<<(total4 + threads - 1) / threads, threads>>>(
                reinterpret_cast<const float4*>(X), total4);
        }
        {
            const int threads = 256;                         // 16 nodes / block
            const int blocks = (n_nodes + 15) / 16;
            sag_fp16_kernel<<<blocks, threads>>>(rp, col, out, n_nodes);
        }
    } else {
        const int threads = 256;
        const int blocks = (n_nodes * 16 + threads - 1) / threads;
        sag_fp32_kernel<<<blocks, threads>>>(X, rp, col, out, n_nodes);
    }
}

// round 6
// speedup vs baseline: 1.4331x; 1.1517x over previous
#include <cuda_runtime.h>
#include <cuda_fp16.h>

// SAG: CSR SpMM neighbor aggregation, deg=16, D=48, fp32 in/out.
//
// R5: R4 was issue-bound (67.9%) on fp32 convert+accumulate (8 warp-instr of
// math per edge-pair). Switch to fp16 HADD2 accumulation: 2 HADD2 per
// edge-pair, 5 warp-instr total per iteration. To keep rounding error well
// under the 1e-3 bound, edges are summed in TWO independent fp16 trees
// (8 edges each) combined in fp32 at the end (predicted rel_err ~4e-4).
// Rows stay unpadded 96B fp16 (32B-aligned -> 3 L2 sectors/edge); memory
// (~180MB through L2 at the ~12.9TB/s LTS cap) re-becomes the binder.

#define N_CAP   100000
#define D_FEAT  48
#define ROW_I2  12            // 96 B row = 12 int2 (4 halves each)

__device__ __align__(16) __half2 g_Xh[(size_t)N_CAP * 24];   // 9.6 MB scratch

// ---- pre-pass: fp32 [n,48] -> fp16 [n,48] (contiguous, vectorized) ---------
__global__ void convert_kernel(const float4* __restrict__ X4, int total4)
{
    int t = blockIdx.x * blockDim.x + threadIdx.x;   // one float4 -> one uint2
    if (t >= total4) return;
    const float4 f = __ldg(X4 + t);
    const __half2 a = __floats2half2_rn(f.x, f.y);
    const __half2 b = __floats2half2_rn(f.z, f.w);
    uint2 v;
    v.x = *reinterpret_cast<const unsigned int*>(&a);
    v.y = *reinterpret_cast<const unsigned int*>(&b);
    reinterpret_cast<uint2*>(g_Xh)[t] = v;
}

// ---- main: 2 nodes per warp, 16 lanes per node, fp16 two-tree accumulate ---
__global__ __launch_bounds__(256, 8)
void sag_fp16_kernel(const int* __restrict__ row_pointers,
                     const int* __restrict__ column_index,
                     float* __restrict__ out,
                     int n_nodes)
{
    const int sub  = threadIdx.x & 15;                  // lane within node group
    const int node = ((blockIdx.x * blockDim.x + threadIdx.x) >> 4);
    if (node >= n_nodes) return;

    const int base = row_pointers[node];
    const int deg  = row_pointers[node + 1] - base;

    // sub-lane e holds edge e's neighbor index (coalesced)
    int my_idx = 0;
    if (sub < deg) my_idx = column_index[base + sub];

    const __half2* __restrict__ Xh = g_Xh;
    const bool active = (sub < ROW_I2);

    if (deg == 16) {
        // Two independent fp16 accumulation trees (edges 0-7 and 8-15),
        // each lane owns 4 halves (2 half2) of the row.
        __half2 t0a = __float2half2_rn(0.f), t0b = __float2half2_rn(0.f);
        __half2 t1a = __float2half2_rn(0.f), t1b = __float2half2_rn(0.f);

        #pragma unroll
        for (int e = 0; e < 16; ++e) {
            const int idx = __shfl_sync(0xffffffffu, my_idx, e, 16);
            if (active) {
                // 1 IMAD.WIDE: byte offset = idx*96 + sub*8
                const int2 v = __ldg(reinterpret_cast<const int2*>(Xh)
                                     + (idx * ROW_I2 + sub));
                const __half2 h0 = *reinterpret_cast<const __half2*>(&v.x);
                const __half2 h1 = *reinterpret_cast<const __half2*>(&v.y);
                if (e < 8) { t0a = __hadd2(t0a, h0); t0b = __hadd2(t0b, h1); }
                else       { t1a = __hadd2(t1a, h0); t1b = __hadd2(t1b, h1); }
            }
        }

        if (active) {
            const float2 f0 = __half22float2(t0a);
            const float2 f1 = __half22float2(t0b);
            const float2 g0 = __half22float2(t1a);
            const float2 g1 = __half22float2(t1b);
            reinterpret_cast<float4*>(out)[node * ROW_I2 + sub] =
                make_float4(f0.x + g0.x, f0.y + g0.y, f1.x + g1.x, f1.y + g1.y);
        }
    } else {
        // Generic fallback (never taken for this dataset): fp32 accumulate.
        float a0 = 0.f, a1 = 0.f, a2 = 0.f, a3 = 0.f;
        for (int e = 0; e < deg; ++e) {
            int idx = (e < 16) ? __shfl_sync(0xffffffffu, my_idx, e, 16)
                               : column_index[base + e];
            if (active) {
                const int2 v = __ldg(reinterpret_cast<const int2*>(Xh)
                                     + (idx * ROW_I2 + sub));
                const float2 f0 = __half22float2(*reinterpret_cast<const __half2*>(&v.x));
                const float2 f1 = __half22float2(*reinterpret_cast<const __half2*>(&v.y));
                a0 += f0.x; a1 += f0.y; a2 += f1.x; a3 += f1.y;
            }
        }
        if (active) {
            reinterpret_cast<float4*>(out)[node * ROW_I2 + sub] =
                make_float4(a0, a1, a2, a3);
        }
    }
}

// ---- fp32 fallback (only if n exceeds scratch capacity) --------------------
__global__ __launch_bounds__(256, 8)
void sag_fp32_kernel(const float* __restrict__ X,
                     const int* __restrict__ row_pointers,
                     const int* __restrict__ column_index,
                     float* __restrict__ out,
                     int n_nodes)
{
    const int tid  = blockIdx.x * blockDim.x + threadIdx.x;
    const int node = tid >> 4;
    const int lane = tid & 15;
    if (node >= n_nodes) return;

    const int base = row_pointers[node];
    const int deg  = row_pointers[node + 1] - base;
    int my_idx = 0;
    if (lane < deg) my_idx = column_index[base + lane];

    float a0 = 0.f, a1 = 0.f, a2 = 0.f;
    for (int e = 0; e < deg; ++e) {
        int idx = (e < 16) ? __shfl_sync(0xffffffffu, my_idx, e, 16)
                           : column_index[base + e];
        const float* row = X + (size_t)idx * D_FEAT;
        a0 += __ldg(row + lane);
        a1 += __ldg(row + lane + 16);
        a2 += __ldg(row + lane + 32);
    }
    float* orow = out + (size_t)node * D_FEAT;
    orow[lane] = a0; orow[lane + 16] = a1; orow[lane + 32] = a2;
}

extern "C" void kernel_launch(void* const* d_in, const int* in_sizes, int n_in,
                              void* d_out, int out_size)
{
    const float* X   = (const float*)d_in[0];
    const int*   rp  = (const int*)d_in[1];
    const int*   col = (const int*)d_in[2];
    float*       out = (float*)d_out;

    const int n_nodes = in_sizes[1] - 1;

    if (n_nodes <= N_CAP) {
        {
            const int total4 = n_nodes * (D_FEAT / 4);      // 1.2M float4
            const int threads = 256;
            convert_kernel<<<(total4 + threads - 1) / threads, threads>>>(
                reinterpret_cast<const float4*>(X), total4);
        }
        {
            const int threads = 256;                         // 16 nodes / block
            const int blocks = (n_nodes + 15) / 16;
            sag_fp16_kernel<<<blocks, threads>>>(rp, col, out, n_nodes);
        }
    } else {
        const int threads = 256;
        const int blocks = (n_nodes * 16 + threads - 1) / threads;
        sag_fp32_kernel<<<blocks, threads>>>(X, rp, col, out, n_nodes);
    }
}

// round 7
// speedup vs baseline: 1.4451x; 1.0083x over previous
#include <cuda_runtime.h>
#include <cuda_fp16.h>

// SAG: CSR SpMM neighbor aggregation, deg=16, D=48, fp32 in/out.
//
// R6: R5's `if (lane<12)` inside the unrolled loop compiled to branch
// envelopes (~3 extra instr/iter -> issue 49.8%). Replace predication with a
// lane CLAMP: lanes 12-15 duplicate lane 11's load (same cache lines -> no
// extra wavefronts or bytes), making the 16-step loop fully branch-free:
// SHFL + IMAD + LDG.64 + 2 HADD2 per iteration. Also relax launch bounds
// (32-reg cap was limiting load hoisting / MLP). fp16 two-tree accumulation
// kept (rel_err ~5e-4, under 1e-3). Memory (~180MB via L2) re-binds at the
// ~12.9TB/s LTS cap -> main ~14-15us.

#define N_CAP   100000
#define D_FEAT  48
#define ROW_I2  12            // 96 B row = 12 int2 (4 halves each)

__device__ __align__(16) __half2 g_Xh[(size_t)N_CAP * 24];   // 9.6 MB scratch

// ---- pre-pass: fp32 [n,48] -> fp16 [n,48] (contiguous, vectorized) ---------
__global__ void convert_kernel(const float4* __restrict__ X4, int total4)
{
    int t = blockIdx.x * blockDim.x + threadIdx.x;   // one float4 -> one uint2
    if (t >= total4) return;
    const float4 f = __ldg(X4 + t);
    const __half2 a = __floats2half2_rn(f.x, f.y);
    const __half2 b = __floats2half2_rn(f.z, f.w);
    uint2 v;
    v.x = *reinterpret_cast<const unsigned int*>(&a);
    v.y = *reinterpret_cast<const unsigned int*>(&b);
    reinterpret_cast<uint2*>(g_Xh)[t] = v;
}

// ---- main: 2 nodes/warp, 16 lanes/node, branch-free fp16 two-tree sum ------
__global__ __launch_bounds__(256, 4)
void sag_fp16_kernel(const int* __restrict__ row_pointers,
                     const int* __restrict__ column_index,
                     float* __restrict__ out,
                     int n_nodes)
{
    const int sub  = threadIdx.x & 15;                  // lane within node group
    const int node = ((blockIdx.x * blockDim.x + threadIdx.x) >> 4);
    if (node >= n_nodes) return;

    const int base = row_pointers[node];
    const int deg  = row_pointers[node + 1] - base;

    // sub-lane e holds edge e's neighbor index (coalesced)
    int my_idx = 0;
    if (sub < deg) my_idx = column_index[base + sub];

    // Lanes 12-15 duplicate lane 11's slot: same cache lines, zero extra
    // traffic, results discarded at store time. Keeps the loop branch-free.
    const int subc = (sub < ROW_I2) ? sub : (ROW_I2 - 1);
    const int2* __restrict__ Xi2 = reinterpret_cast<const int2*>(g_Xh);

    if (deg == 16) {
        // Two independent fp16 trees (edges 0-7, 8-15) combined in fp32.
        __half2 t0a = __float2half2_rn(0.f), t0b = __float2half2_rn(0.f);
        __half2 t1a = __float2half2_rn(0.f), t1b = __float2half2_rn(0.f);

        #pragma unroll
        for (int e = 0; e < 16; ++e) {
            const int idx = __shfl_sync(0xffffffffu, my_idx, e, 16);
            const int2 v = __ldg(Xi2 + (idx * ROW_I2 + subc));
            const __half2 h0 = *reinterpret_cast<const __half2*>(&v.x);
            const __half2 h1 = *reinterpret_cast<const __half2*>(&v.y);
            if (e < 8) { t0a = __hadd2(t0a, h0); t0b = __hadd2(t0b, h1); }
            else       { t1a = __hadd2(t1a, h0); t1b = __hadd2(t1b, h1); }
        }

        if (sub < ROW_I2) {
            const float2 f0 = __half22float2(t0a);
            const float2 f1 = __half22float2(t0b);
            const float2 g0 = __half22float2(t1a);
            const float2 g1 = __half22float2(t1b);
            reinterpret_cast<float4*>(out)[node * ROW_I2 + sub] =
                make_float4(f0.x + g0.x, f0.y + g0.y, f1.x + g1.x, f1.y + g1.y);
        }
    } else {
        // Generic fallback (never taken here): fp32 accumulate.
        float a0 = 0.f, a1 = 0.f, a2 = 0.f, a3 = 0.f;
        for (int e = 0; e < deg; ++e) {
            int idx = (e < 16) ? __shfl_sync(0xffffffffu, my_idx, e, 16)
                               : column_index[base + e];
            const int2 v = __ldg(Xi2 + (idx * ROW_I2 + subc));
            const float2 f0 = __half22float2(*reinterpret_cast<const __half2*>(&v.x));
            const float2 f1 = __half22float2(*reinterpret_cast<const __half2*>(&v.y));
            a0 += f0.x; a1 += f0.y; a2 += f1.x; a3 += f1.y;
        }
        if (sub < ROW_I2) {
            reinterpret_cast<float4*>(out)[node * ROW_I2 + sub] =
                make_float4(a0, a1, a2, a3);
        }
    }
}

// ---- fp32 fallback (only if n exceeds scratch capacity) --------------------
__global__ __launch_bounds__(256, 8)
void sag_fp32_kernel(const float* __restrict__ X,
                     const int* __restrict__ row_pointers,
                     const int* __restrict__ column_index,
                     float* __restrict__ out,
                     int n_nodes)
{
    const int tid  = blockIdx.x * blockDim.x + threadIdx.x;
    const int node = tid >> 4;
    const int lane = tid & 15;
    if (node >= n_nodes) return;

    const int base = row_pointers[node];
    const int deg  = row_pointers[node + 1] - base;
    int my_idx = 0;
    if (lane < deg) my_idx = column_index[base + lane];

    float a0 = 0.f, a1 = 0.f, a2 = 0.f;
    for (int e = 0; e < deg; ++e) {
        int idx = (e < 16) ? __shfl_sync(0xffffffffu, my_idx, e, 16)
                           : column_index[base + e];
        const float* row = X + (size_t)idx * D_FEAT;
        a0 += __ldg(row + lane);
        a1 += __ldg(row + lane + 16);
        a2 += __ldg(row + lane + 32);
    }
    float* orow = out + (size_t)node * D_FEAT;
    orow[lane] = a0; orow[lane + 16] = a1; orow[lane + 32] = a2;
}

extern "C" void kernel_launch(void* const* d_in, const int* in_sizes, int n_in,
                              void* d_out, int out_size)
{
    const float* X   = (const float*)d_in[0];
    const int*   rp  = (const int*)d_in[1];
    const int*   col = (const int*)d_in[2];
    float*       out = (float*)d_out;

    const int n_nodes = in_sizes[1] - 1;

    if (n_nodes <= N_CAP) {
        {
            const int total4 = n_nodes * (D_FEAT / 4);      // 1.2M float4
            const int threads = 256;
            convert_kernel<<<(total4 + threads - 1) / threads, threads>>>(
                reinterpret_cast<const float4*>(X), total4);
        }
        {
            const int threads = 256;                         // 16 nodes / block
            const int blocks = (n_nodes + 15) / 16;
            sag_fp16_kernel<<<blocks, threads>>>(rp, col, out, n_nodes);
        }
    } else {
        const int threads = 256;
        const int blocks = (n_nodes * 16 + threads - 1) / threads;
        sag_fp32_kernel<<<blocks, threads>>>(X, rp, col, out, n_nodes);
    }
}

// round 9
// speedup vs baseline: 1.4717x; 1.0184x over previous
#include <cuda_runtime.h>
#include <cuda_fp16.h>

// SAG: CSR SpMM neighbor aggregation, deg=16, D=48, fp32 in/out.
//
// R7: combine the two orthogonal wins.
//  - R6's branch-free loop body (lane clamp instead of `if(lane<12)`:
//    lanes 12-15 duplicate lane 11's load -> same cache lines, zero extra
//    traffic; 5 warp-instr/iter: SHFL + IMAD + LDG.64 + 2 HADD2).
//  - R5's occupancy: __launch_bounds__(256,8) caps regs at 32 -> ~85%
//    achieved occupancy. R6 showed that at 42 regs / 54% occ the kernel is
//    latency-bound (everything <45%); 68 warps/SM x MLP~4 covers the ~240cyc
//    L2-hit latency.
// fp16 two-tree accumulation (rel_err ~5e-4 < 1e-3). ~180MB through L2 at
// the ~12.9TB/s LTS cap -> main ~15us.

#define N_CAP   100000
#define D_FEAT  48
#define ROW_I2  12            // 96 B row = 12 int2 (4 halves each)

__device__ __align__(16) __half2 g_Xh[(size_t)N_CAP * 24];   // 9.6 MB scratch

// ---- pre-pass: fp32 [n,48] -> fp16 [n,48] (contiguous, vectorized) ---------
__global__ void convert_kernel(const float4* __restrict__ X4, int total4)
{
    int t = blockIdx.x * blockDim.x + threadIdx.x;   // one float4 -> one uint2
    if (t >= total4) return;
    const float4 f = __ldg(X4 + t);
    const __half2 a = __floats2half2_rn(f.x, f.y);
    const __half2 b = __floats2half2_rn(f.z, f.w);
    uint2 v;
    v.x = *reinterpret_cast<const unsigned int*>(&a);
    v.y = *reinterpret_cast<const unsigned int*>(&b);
    reinterpret_cast<uint2*>(g_Xh)[t] = v;
}

// ---- main: 2 nodes/warp, 16 lanes/node, branch-free fp16 two-tree sum ------
__global__ __launch_bounds__(256, 8)
void sag_fp16_kernel(const int* __restrict__ row_pointers,
                     const int* __restrict__ column_index,
                     float* __restrict__ out,
                     int n_nodes)
{
    const int sub  = threadIdx.x & 15;                  // lane within node group
    const int node = ((blockIdx.x * blockDim.x + threadIdx.x) >> 4);
    if (node >= n_nodes) return;

    const int base = row_pointers[node];
    const int deg  = row_pointers[node + 1] - base;

    // sub-lane e holds edge e's neighbor index (coalesced)
    int my_idx = 0;
    if (sub < deg) my_idx = column_index[base + sub];

    // Lanes 12-15 duplicate lane 11's slot: same cache lines, zero extra
    // traffic, results discarded at store time. Keeps the loop branch-free.
    const int subc = (sub < ROW_I2) ? sub : (ROW_I2 - 1);
    const int2* __restrict__ Xi2 = reinterpret_cast<const int2*>(g_Xh);

    if (deg == 16) {
        // Two independent fp16 trees (edges 0-7, 8-15) combined in fp32.
        __half2 t0a = __float2half2_rn(0.f), t0b = __float2half2_rn(0.f);
        __half2 t1a = __float2half2_rn(0.f), t1b = __float2half2_rn(0.f);

        #pragma unroll
        for (int e = 0; e < 16; ++e) {
            const int idx = __shfl_sync(0xffffffffu, my_idx, e, 16);
            const int2 v = __ldg(Xi2 + (idx * ROW_I2 + subc));
            const __half2 h0 = *reinterpret_cast<const __half2*>(&v.x);
            const __half2 h1 = *reinterpret_cast<const __half2*>(&v.y);
            if (e < 8) { t0a = __hadd2(t0a, h0); t0b = __hadd2(t0b, h1); }
            else       { t1a = __hadd2(t1a, h0); t1b = __hadd2(t1b, h1); }
        }

        if (sub < ROW_I2) {
            const float2 f0 = __half22float2(t0a);
            const float2 f1 = __half22float2(t0b);
            const float2 g0 = __half22float2(t1a);
            const float2 g1 = __half22float2(t1b);
            reinterpret_cast<float4*>(out)[node * ROW_I2 + sub] =
                make_float4(f0.x + g0.x, f0.y + g0.y, f1.x + g1.x, f1.y + g1.y);
        }
    } else {
        // Generic fallback (never taken here): fp32 accumulate.
        float a0 = 0.f, a1 = 0.f, a2 = 0.f, a3 = 0.f;
        for (int e = 0; e < deg; ++e) {
            int idx = (e < 16) ? __shfl_sync(0xffffffffu, my_idx, e, 16)
                               : column_index[base + e];
            const int2 v = __ldg(Xi2 + (idx * ROW_I2 + subc));
            const float2 f0 = __half22float2(*reinterpret_cast<const __half2*>(&v.x));
            const float2 f1 = __half22float2(*reinterpret_cast<const __half2*>(&v.y));
            a0 += f0.x; a1 += f0.y; a2 += f1.x; a3 += f1.y;
        }
        if (sub < ROW_I2) {
            reinterpret_cast<float4*>(out)[node * ROW_I2 + sub] =
                make_float4(a0, a1, a2, a3);
        }
    }
}

// ---- fp32 fallback (only if n exceeds scratch capacity) --------------------
__global__ __launch_bounds__(256, 8)
void sag_fp32_kernel(const float* __restrict__ X,
                     const int* __restrict__ row_pointers,
                     const int* __restrict__ column_index,
                     float* __restrict__ out,
                     int n_nodes)
{
    const int tid  = blockIdx.x * blockDim.x + threadIdx.x;
    const int node = tid >> 4;
    const int lane = tid & 15;
    if (node >= n_nodes) return;

    const int base = row_pointers[node];
    const int deg  = row_pointers[node + 1] - base;
    int my_idx = 0;
    if (lane < deg) my_idx = column_index[base + lane];

    float a0 = 0.f, a1 = 0.f, a2 = 0.f;
    for (int e = 0; e < deg; ++e) {
        int idx = (e < 16) ? __shfl_sync(0xffffffffu, my_idx, e, 16)
                           : column_index[base + e];
        const float* row = X + (size_t)idx * D_FEAT;
        a0 += __ldg(row + lane);
        a1 += __ldg(row + lane + 16);
        a2 += __ldg(row + lane + 32);
    }
    float* orow = out + (size_t)node * D_FEAT;
    orow[lane] = a0; orow[lane + 16] = a1; orow[lane + 32] = a2;
}

extern "C" void kernel_launch(void* const* d_in, const int* in_sizes, int n_in,
                              void* d_out, int out_size)
{
    const float* X   = (const float*)d_in[0];
    const int*   rp  = (const int*)d_in[1];
    const int*   col = (const int*)d_in[2];
    float*       out = (float*)d_out;

    const int n_nodes = in_sizes[1] - 1;

    if (n_nodes <= N_CAP) {
        {
            const int total4 = n_nodes * (D_FEAT / 4);      // 1.2M float4
            const int threads = 256;
            convert_kernel<<<(total4 + threads - 1) / threads, threads>>>(
                reinterpret_cast<const float4*>(X), total4);
        }
        {
            const int threads = 256;                         // 16 nodes / block
            const int blocks = (n_nodes + 15) / 16;
            sag_fp16_kernel<<<blocks, threads>>>(rp, col, out, n_nodes);
        }
    } else {
        const int threads = 256;
        const int blocks = (n_nodes * 16 + threads - 1) / threads;
        sag_fp32_kernel<<<blocks, threads>>>(X, rp, col, out, n_nodes);
    }
}